// round 17
// baseline (speedup 1.0000x reference)
#include <cuda_runtime.h>
#include <cuda_fp16.h>
#include <cuda_bf16.h>
#include <math.h>
#include <cstdint>

// ---------------------------------------------------------------------------
// TemporalMamba: B=2, L=1024, D_MODEL=1024, D_INNER=2048, D_STATE=16,
// D_CONV=4, DT_RANK=64.
// GEMMs: mma.sync fp16x2 split (rel_err 3.6e-4, gate 1e-3).
// Scan: SEGMENTED linear recurrence (4 segments): scanA (h_end, A_cum) ->
//   combine (exact segment-entry h0) -> scanB (y output).  4x time-parallel.
// ---------------------------------------------------------------------------

#define BB       2
#define LL       1024
#define DMODEL   1024
#define DINNER   2048
#define DSTATE   16
#define DTRANK   64
#define MROWS    (BB * LL)                  // 2048
#define XPROJ_N  (DTRANK + 2 * DSTATE)      // 96
#define KSPLITS  16
#define NSEG     4
#define SEG      (LL / NSEG)                // 256
#define SCT      32

// ------------------------- scratch (device globals) ------------------------
__device__ float g_xz[MROWS * 2 * DINNER];      // [M, 4096]
__device__ float g_u[MROWS * DINNER];           // [M, 2048]
__device__ float g_xdbl[MROWS * XPROJ_N];       // [M, 96]
__device__ float g_xpart[KSPLITS * MROWS * XPROJ_N];
__device__ float g_part[2 * MROWS * DMODEL];    // GEMM4 split-K partials
__device__ float g_delta[MROWS * DINNER];       // delta (scanA -> scanB)
__device__ float g_hend[BB * NSEG * DINNER * DSTATE];
__device__ float g_acum[BB * NSEG * DINNER * DSTATE];
__device__ float g_h0[BB * NSEG * DINNER * DSTATE];

// fp16 operands
__device__ __half g_xh[MROWS * DMODEL];
__device__ __half g_winT_h[4096 * DMODEL];
__device__ __half g_winT_l[4096 * DMODEL];
__device__ __half g_yh[MROWS * DINNER];
__device__ __half g_woutT_h[DMODEL * DINNER];
__device__ __half g_woutT_l[DMODEL * DINNER];

// ---------------------------------------------------------------------------
// helpers
// ---------------------------------------------------------------------------
__device__ __forceinline__ uint32_t smem_u32(const void* p) {
    uint32_t a;
    asm("{ .reg .u64 t; cvta.to.shared.u64 t, %1; cvt.u32.u64 %0, t; }" : "=r"(a) : "l"(p));
    return a;
}
__device__ __forceinline__ void cpa16(uint32_t s, const void* g) {
    asm volatile("cp.async.cg.shared.global [%0], [%1], 16;" :: "r"(s), "l"(g));
}
__device__ __forceinline__ void cpa4(uint32_t s, const void* g) {
    asm volatile("cp.async.ca.shared.global [%0], [%1], 4;" :: "r"(s), "l"(g));
}
__device__ __forceinline__ void ldsm4(uint32_t& r0, uint32_t& r1, uint32_t& r2, uint32_t& r3,
                                      uint32_t addr) {
    asm volatile("ldmatrix.sync.aligned.m8n8.x4.shared.b16 {%0,%1,%2,%3}, [%4];"
                 : "=r"(r0), "=r"(r1), "=r"(r2), "=r"(r3) : "r"(addr));
}
__device__ __forceinline__ void mma16816(float& c0, float& c1, float& c2, float& c3,
                                         uint32_t a0, uint32_t a1, uint32_t a2, uint32_t a3,
                                         uint32_t b0, uint32_t b1) {
    asm volatile(
        "mma.sync.aligned.m16n8k16.row.col.f32.f16.f16.f32 "
        "{%0,%1,%2,%3}, {%4,%5,%6,%7}, {%8,%9}, {%0,%1,%2,%3};"
        : "+f"(c0), "+f"(c1), "+f"(c2), "+f"(c3)
        : "r"(a0), "r"(a1), "r"(a2), "r"(a3), "r"(b0), "r"(b1));
}

// ---------------------------------------------------------------------------
// fp16x2 split tensor-core GEMM (R16, measured best: BK=64, 2 CTAs/SM)
// ---------------------------------------------------------------------------
#define SSTR     72
#define TILE_B   (128 * SSTR * 2)                    // 18432 B
#define STAGE_B  (3 * TILE_B)                        // 55296 B
#define GM_SMEM  (2 * STAGE_B)                       // 110592 B

__device__ __forceinline__ void load_stage_tile(
    const __half* __restrict__ G, int rowBase, int k0, int K,
    uint32_t sdst, int tid)
{
#pragma unroll
    for (int i = 0; i < 4; i++) {
        int idx = tid + i * 256;
        int r = idx >> 3;
        int q = idx & 7;
        const void* g = G + (size_t)(rowBase + r) * K + k0 + q * 8;
        cpa16(sdst + (uint32_t)(r * SSTR + q * 8) * 2, g);
    }
}

__global__ __launch_bounds__(256, 2)
void gemm_mma(const __half* __restrict__ A,
              const __half* __restrict__ Bh, const __half* __restrict__ Bl,
              float* __restrict__ C, int Kfull, int ldc, int kdepth,
              size_t partStride)
{
    extern __shared__ __align__(16) char dsm[];
    const uint32_t sbase = smem_u32(dsm);

    const int tid  = threadIdx.x;
    const int wid  = tid >> 5;
    const int lane = tid & 31;
    const int wm   = wid >> 2;
    const int wn   = wid & 3;
    const int bx   = blockIdx.x, by = blockIdx.y;
    const int kbase = blockIdx.z * kdepth;
    C += (size_t)blockIdx.z * partStride;

    const int aRow  = lane & 15;
    const int aCsel = (lane >> 4) * 8;
    const int bRow  = (lane & 7) + ((lane >> 4) << 3);
    const int bCsel = ((lane >> 3) & 1) * 8;

    float acc[4][4][4];
#pragma unroll
    for (int i = 0; i < 4; i++)
#pragma unroll
        for (int j = 0; j < 4; j++)
#pragma unroll
            for (int v = 0; v < 4; v++) acc[i][j][v] = 0.f;

    const int NC = kdepth >> 6;

    load_stage_tile(A,  by * 128, kbase, Kfull, sbase + 0 * TILE_B, tid);
    load_stage_tile(Bh, bx * 128, kbase, Kfull, sbase + 1 * TILE_B, tid);
    load_stage_tile(Bl, bx * 128, kbase, Kfull, sbase + 2 * TILE_B, tid);
    asm volatile("cp.async.commit_group;");

    for (int c = 0; c < NC; c++) {
        if (c + 1 < NC) {
            const uint32_t sd = sbase + ((c + 1) & 1) * STAGE_B;
            const int k0 = kbase + ((c + 1) << 6);
            load_stage_tile(A,  by * 128, k0, Kfull, sd + 0 * TILE_B, tid);
            load_stage_tile(Bh, bx * 128, k0, Kfull, sd + 1 * TILE_B, tid);
            load_stage_tile(Bl, bx * 128, k0, Kfull, sd + 2 * TILE_B, tid);
            asm volatile("cp.async.commit_group;");
            asm volatile("cp.async.wait_group 1;");
        } else {
            asm volatile("cp.async.wait_group 0;");
        }
        __syncthreads();

        const uint32_t st  = sbase + (c & 1) * STAGE_B;
        const uint32_t sA  = st;
        const uint32_t sBh = st + 1 * TILE_B;
        const uint32_t sBl = st + 2 * TILE_B;

#pragma unroll
        for (int kk = 0; kk < 64; kk += 16) {
            uint32_t a[4][4], bh[2][4], bl[2][4];
#pragma unroll
            for (int i = 0; i < 4; i++) {
                uint32_t off = (uint32_t)((wm * 64 + i * 16 + aRow) * SSTR + kk + aCsel) * 2;
                ldsm4(a[i][0], a[i][1], a[i][2], a[i][3], sA + off);
            }
#pragma unroll
            for (int j2 = 0; j2 < 2; j2++) {
                uint32_t off = (uint32_t)((wn * 32 + j2 * 16 + bRow) * SSTR + kk + bCsel) * 2;
                ldsm4(bh[j2][0], bh[j2][1], bh[j2][2], bh[j2][3], sBh + off);
            }
#pragma unroll
            for (int j2 = 0; j2 < 2; j2++) {
                uint32_t off = (uint32_t)((wn * 32 + j2 * 16 + bRow) * SSTR + kk + bCsel) * 2;
                ldsm4(bl[j2][0], bl[j2][1], bl[j2][2], bl[j2][3], sBl + off);
            }
#pragma unroll
            for (int i = 0; i < 4; i++)
#pragma unroll
                for (int j = 0; j < 4; j++) {
                    const uint32_t* b = bh[j >> 1] + (j & 1) * 2;
                    mma16816(acc[i][j][0], acc[i][j][1], acc[i][j][2], acc[i][j][3],
                             a[i][0], a[i][1], a[i][2], a[i][3], b[0], b[1]);
                }
#pragma unroll
            for (int i = 0; i < 4; i++)
#pragma unroll
                for (int j = 0; j < 4; j++) {
                    const uint32_t* b = bl[j >> 1] + (j & 1) * 2;
                    mma16816(acc[i][j][0], acc[i][j][1], acc[i][j][2], acc[i][j][3],
                             a[i][0], a[i][1], a[i][2], a[i][3], b[0], b[1]);
                }
        }
        __syncthreads();
    }

    const int mBase = by * 128 + wm * 64;
    const int nBase = bx * 128 + wn * 32;
    const int r0 = lane >> 2;
    const int c0 = (lane & 3) * 2;
#pragma unroll
    for (int i = 0; i < 4; i++) {
#pragma unroll
        for (int j = 0; j < 4; j++) {
            float* p0 = C + (size_t)(mBase + i * 16 + r0) * ldc + nBase + j * 8 + c0;
            *(float2*)p0                     = make_float2(acc[i][j][0], acc[i][j][1]);
            *(float2*)(p0 + (size_t)8 * ldc) = make_float2(acc[i][j][2], acc[i][j][3]);
        }
    }
}

// fixed-order split-K reduce
__global__ __launch_bounds__(256)
void reduce2(const float* __restrict__ part, float* __restrict__ out, int n)
{
    int i = (blockIdx.x * 256 + threadIdx.x) * 4;
    if (i >= n) return;
    float4 a = *(const float4*)(part + i);
    float4 b = *(const float4*)(part + (size_t)n + i);
    *(float4*)(out + i) = make_float4(a.x + b.x, a.y + b.y, a.z + b.z, a.w + b.w);
}

// ---------------------------------------------------------------------------
// conversions
// ---------------------------------------------------------------------------
__global__ __launch_bounds__(256)
void conv_fp16(const float* __restrict__ in, __half* __restrict__ out, int n4)
{
    int i = blockIdx.x * 256 + threadIdx.x;
    if (i >= n4) return;
    float4 v = *(const float4*)(in + i * 4);
    __half2* p = (__half2*)(out + i * 4);
    p[0] = __half2(__float2half(v.x), __float2half(v.y));
    p[1] = __half2(__float2half(v.z), __float2half(v.w));
}

__global__ __launch_bounds__(256)
void tsplit_fp16(const float* __restrict__ in,
                 __half* __restrict__ hiT, __half* __restrict__ loT,
                 int K, int N)
{
    __shared__ float t[32][33];
    int tx = threadIdx.x & 31;
    int ty = threadIdx.x >> 5;
    int n0 = blockIdx.x * 32;
    int k0 = blockIdx.y * 32;
#pragma unroll
    for (int j = 0; j < 4; j++) {
        int kk = ty + j * 8;
        t[kk][tx] = in[(size_t)(k0 + kk) * N + n0 + tx];
    }
    __syncthreads();
#pragma unroll
    for (int j = 0; j < 4; j++) {
        int a = ty + j * 8;
        float v = t[tx][a];
        __half h = __float2half(v);
        hiT[(size_t)(n0 + a) * K + k0 + tx] = h;
        loT[(size_t)(n0 + a) * K + k0 + tx] = __float2half(v - __half2float(h));
    }
}

// ---------------------------------------------------------------------------
// depthwise conv(4) + bias + silu
// ---------------------------------------------------------------------------
__global__ __launch_bounds__(256)
void conv_silu_kernel(const float* __restrict__ xz,
                      const float* __restrict__ cw,
                      const float* __restrict__ cb,
                      float* __restrict__ u)
{
    int idx = blockIdx.x * blockDim.x + threadIdx.x;
    if (idx >= MROWS * DINNER / 4) return;
    int d4  = (idx & (DINNER / 4 - 1)) * 4;
    int row = idx >> 9;
    int l   = row & (LL - 1);

    float4 w0 = *(const float4*)(cw + d4 * 4 + 0);
    float4 w1 = *(const float4*)(cw + d4 * 4 + 4);
    float4 w2 = *(const float4*)(cw + d4 * 4 + 8);
    float4 w3 = *(const float4*)(cw + d4 * 4 + 12);
    float4 bias = *(const float4*)(cb + d4);

    const float* base = xz + (size_t)row * (2 * DINNER) + d4;
    const int stride = 2 * DINNER;

    float4 s = bias;
    if (l >= 3) {
        float4 v = *(const float4*)(base - 3 * stride);
        s.x += v.x * w0.x; s.y += v.y * w1.x; s.z += v.z * w2.x; s.w += v.w * w3.x;
    }
    if (l >= 2) {
        float4 v = *(const float4*)(base - 2 * stride);
        s.x += v.x * w0.y; s.y += v.y * w1.y; s.z += v.z * w2.y; s.w += v.w * w3.y;
    }
    if (l >= 1) {
        float4 v = *(const float4*)(base - 1 * stride);
        s.x += v.x * w0.z; s.y += v.y * w1.z; s.z += v.z * w2.z; s.w += v.w * w3.z;
    }
    {
        float4 v = *(const float4*)(base);
        s.x += v.x * w0.w; s.y += v.y * w1.w; s.z += v.z * w2.w; s.w += v.w * w3.w;
    }
    float4 r;
    r.x = s.x / (1.f + expf(-s.x));
    r.y = s.y / (1.f + expf(-s.y));
    r.z = s.z / (1.f + expf(-s.z));
    r.w = s.w / (1.f + expf(-s.w));
    *(float4*)(u + (size_t)row * DINNER + d4) = r;
}

// ---------------------------------------------------------------------------
// xproj split-K (16-way)
// ---------------------------------------------------------------------------
#define XKD (DINNER / KSPLITS)             // 128
__global__ __launch_bounds__(256)
void xprojA(const float* __restrict__ u, const float* __restrict__ W,
            float* __restrict__ part)
{
    __shared__ float As[64 * 32];
    __shared__ float Bs[96 * 36];

    const int ks = blockIdx.x;
    const int mb = blockIdx.y;
    const int tid = threadIdx.x;
    const int rg = tid >> 4;
    const int cg = tid & 15;

    float acc[4][6];
#pragma unroll
    for (int r = 0; r < 4; r++)
#pragma unroll
        for (int j = 0; j < 6; j++) acc[r][j] = 0.f;

    for (int kc = 0; kc < XKD / 32; kc++) {
        const int kbase = ks * XKD + kc * 32;
#pragma unroll
        for (int i = tid; i < 64 * 32; i += 256) {
            int r = i >> 5, k = i & 31;
            As[r * 32 + k] = u[(size_t)(mb * 64 + r) * DINNER + kbase + k];
        }
#pragma unroll
        for (int i = tid; i < 96 * 32; i += 256) {
            int c = i % 96, k = i / 96;
            Bs[c * 36 + k] = W[(size_t)(kbase + k) * XPROJ_N + c];
        }
        __syncthreads();
#pragma unroll
        for (int kq = 0; kq < 8; kq++) {
            float4 a[4], b[6];
#pragma unroll
            for (int r = 0; r < 4; r++)
                a[r] = *(const float4*)&As[(rg * 4 + r) * 32 + kq * 4];
#pragma unroll
            for (int j = 0; j < 6; j++)
                b[j] = *(const float4*)&Bs[(j * 16 + cg) * 36 + kq * 4];
#pragma unroll
            for (int r = 0; r < 4; r++)
#pragma unroll
                for (int j = 0; j < 6; j++)
                    acc[r][j] += a[r].x * b[j].x + a[r].y * b[j].y
                               + a[r].z * b[j].z + a[r].w * b[j].w;
        }
        __syncthreads();
    }
#pragma unroll
    for (int r = 0; r < 4; r++)
#pragma unroll
        for (int j = 0; j < 6; j++)
            part[((size_t)ks * MROWS + mb * 64 + rg * 4 + r) * XPROJ_N + j * 16 + cg]
                = acc[r][j];
}

__global__ __launch_bounds__(256)
void xprojB(const float* __restrict__ part, float* __restrict__ xdbl)
{
    int idx = blockIdx.x * 256 + threadIdx.x;
    if (idx >= MROWS * XPROJ_N) return;
    float s = 0.f;
#pragma unroll
    for (int ks = 0; ks < KSPLITS; ks++)
        s += part[(size_t)ks * MROWS * XPROJ_N + idx];
    xdbl[idx] = s;
}

// ---------------------------------------------------------------------------
// scanA: per segment, compute delta (stored), recurrence from h0=0,
//        emit (h_end, A_cum).  grid (128, BB, NSEG) = 1024 CTAs, ~31KB smem.
// ---------------------------------------------------------------------------
#define A_OFF_W     0                      // [64][16]  1024
#define A_OFF_BD    1024                   // [16]
#define A_OFF_STG   1040
#define A_STG_DT    0                      // 2048
#define A_STG_U     2048                   // 512
#define A_STG_B     2560                   // 512
#define A_STG_SIZE  3072
#define A_OFF_DEL   (A_OFF_STG + 2 * A_STG_SIZE)   // 7184
#define SCANA_SMEM  ((A_OFF_DEL + 512) * 4)        // 30784 B

__global__ __launch_bounds__(256)
void scanA(const float* __restrict__ u,
           const float* __restrict__ xdbl,
           const float* __restrict__ W_dt,
           const float* __restrict__ b_dt,
           const float* __restrict__ A_log,
           float* __restrict__ delta_out,
           float* __restrict__ hend,
           float* __restrict__ acum)
{
    extern __shared__ float sm[];
    float* sW   = sm + A_OFF_W;
    float* sbd  = sm + A_OFF_BD;
    float* sDel = sm + A_OFF_DEL;
    const uint32_t smb = smem_u32(sm);

    const int tid = threadIdx.x;
    const int tn = tid & 15;
    const int td = tid >> 4;
    const int dbase = blockIdx.x * 16;
    const int b = blockIdx.y;
    const int seg = blockIdx.z;
    const int tstart = seg * SEG;

    for (int i = tid; i < 1024; i += 256) {
        int r = i >> 4, c = i & 15;
        sW[i] = W_dt[(size_t)r * DINNER + dbase + c];
    }
    if (tid < 16) sbd[tid] = b_dt[dbase + tid];
    const float Aq = -expf(A_log[(dbase + td) * DSTATE + tn]);

    auto stage = [&](int buf, int t0) {
        const uint32_t sb = smb + (uint32_t)(A_OFF_STG + buf * A_STG_SIZE) * 4;
#pragma unroll
        for (int i = tid; i < SCT * 16; i += 256) {
            int r = i >> 4, c = i & 15;
            int row = b * LL + t0 + r;
            cpa4(sb + (uint32_t)(A_STG_U + i) * 4, u    + (size_t)row * DINNER + dbase + c);
            cpa4(sb + (uint32_t)(A_STG_B + i) * 4, xdbl + (size_t)row * XPROJ_N + DTRANK + c);
        }
#pragma unroll
        for (int i = tid; i < SCT * 64; i += 256) {
            int r = i >> 6, k = i & 63;
            cpa4(sb + (uint32_t)(A_STG_DT + i) * 4,
                 xdbl + (size_t)(b * LL + t0 + r) * XPROJ_N + k);
        }
        asm volatile("cp.async.commit_group;");
    };

    stage(0, tstart);
    __syncthreads();

    float h = 0.f, aC = 1.f;
    const int NCH = SEG / SCT;             // 8

    for (int c = 0; c < NCH; c++) {
        if (c + 1 < NCH) {
            stage((c + 1) & 1, tstart + (c + 1) * SCT);
            asm volatile("cp.async.wait_group 1;");
        } else {
            asm volatile("cp.async.wait_group 0;");
        }
        __syncthreads();

        float* sDT = sm + A_OFF_STG + (c & 1) * A_STG_SIZE + A_STG_DT;
        float* sU  = sm + A_OFF_STG + (c & 1) * A_STG_SIZE + A_STG_U;
        float* sB  = sm + A_OFF_STG + (c & 1) * A_STG_SIZE + A_STG_B;
        const int t0 = tstart + c * SCT;

        // fused delta + store to global for scanB
        {
            const int cc = tid & 15;
            const int r0 = tid >> 4;
            float s0 = sbd[cc], s1 = sbd[cc];
#pragma unroll 8
            for (int k = 0; k < 64; k++) {
                float w = sW[k * 16 + cc];
                s0 += sDT[r0 * 64 + k] * w;
                s1 += sDT[(r0 + 16) * 64 + k] * w;
            }
            float d0 = (s0 > 20.f) ? s0 : log1pf(expf(s0));
            float d1 = (s1 > 20.f) ? s1 : log1pf(expf(s1));
            sDel[r0 * 16 + cc]        = d0;
            sDel[(r0 + 16) * 16 + cc] = d1;
            int row0 = b * LL + t0 + r0;
            delta_out[(size_t)row0 * DINNER + dbase + cc]        = d0;
            delta_out[(size_t)(row0 + 16) * DINNER + dbase + cc] = d1;
        }
        __syncthreads();

#pragma unroll 8
        for (int tt = 0; tt < SCT; tt++) {
            float dlt = sDel[tt * 16 + td];
            float uu  = sU[tt * 16 + td];
            float bb  = sB[tt * 16 + tn];
            float dA  = __expf(dlt * Aq);
            h = dA * h + (dlt * uu) * bb;
            aC *= dA;
        }
        __syncthreads();       // protect sDel before next chunk's delta write
    }

    size_t o = ((size_t)(b * NSEG + seg) * DINNER + dbase + td) * DSTATE + tn;
    hend[o] = h;
    acum[o] = aC;
}

// ---------------------------------------------------------------------------
// scan_combine: exact segment-entry states.  h0[0]=0; h0[s]=aC[s-1]h0[s-1]+he[s-1]
// ---------------------------------------------------------------------------
__global__ __launch_bounds__(256)
void scan_combine(const float* __restrict__ hend, const float* __restrict__ acum,
                  float* __restrict__ h0)
{
    int idx = blockIdx.x * 256 + threadIdx.x;     // < BB*DINNER*16 = 65536
    if (idx >= BB * DINNER * DSTATE) return;
    int n = idx & 15;
    int d = (idx >> 4) & (DINNER - 1);
    int b = idx >> 15;
    float h = 0.f;
#pragma unroll
    for (int s = 0; s < NSEG; s++) {
        size_t o = ((size_t)(b * NSEG + s) * DINNER + d) * DSTATE + n;
        h0[o] = h;
        h = acum[o] * h + hend[o];
    }
}

// ---------------------------------------------------------------------------
// scanB: per segment, recurrence from true h0, write y (fp16).
//   grid (128, BB, NSEG), 55360 B smem (4 CTAs/SM).
// ---------------------------------------------------------------------------
#define B_OFF_DSK   0                      // [16]
#define B_OFF_STG   16
#define B_STG_DEL   0                      // 512
#define B_STG_U     512
#define B_STG_Z     1024
#define B_STG_B     1536
#define B_STG_C     2048
#define B_STG_SIZE  2560
#define B_OFF_P     (B_OFF_STG + 2 * B_STG_SIZE)   // 5136
#define SCANB_SMEM  ((B_OFF_P + 8704) * 4)         // 55360 B

__global__ __launch_bounds__(256)
void scanB(const float* __restrict__ u,
           const float* __restrict__ xz,
           const float* __restrict__ xdbl,
           const float* __restrict__ delta,
           const float* __restrict__ A_log,
           const float* __restrict__ Dskip,
           const float* __restrict__ h0arr,
           __half* __restrict__ yh)
{
    extern __shared__ float sm[];
    float* sdsk = sm + B_OFF_DSK;
    float* sP   = sm + B_OFF_P;
    const uint32_t smb = smem_u32(sm);

    const int tid = threadIdx.x;
    const int tn = tid & 15;
    const int td = tid >> 4;
    const int dbase = blockIdx.x * 16;
    const int b = blockIdx.y;
    const int seg = blockIdx.z;
    const int tstart = seg * SEG;

    if (tid < 16) sdsk[tid] = Dskip[dbase + tid];
    const float Aq = -expf(A_log[(dbase + td) * DSTATE + tn]);
    float h = h0arr[((size_t)(b * NSEG + seg) * DINNER + dbase + td) * DSTATE + tn];

    auto stage = [&](int buf, int t0) {
        const uint32_t sb = smb + (uint32_t)(B_OFF_STG + buf * B_STG_SIZE) * 4;
#pragma unroll
        for (int i = tid; i < SCT * 16; i += 256) {
            int r = i >> 4, c = i & 15;
            int row = b * LL + t0 + r;
            cpa4(sb + (uint32_t)(B_STG_DEL + i) * 4, delta + (size_t)row * DINNER + dbase + c);
            cpa4(sb + (uint32_t)(B_STG_U   + i) * 4, u     + (size_t)row * DINNER + dbase + c);
            cpa4(sb + (uint32_t)(B_STG_Z   + i) * 4, xz    + (size_t)row * (2 * DINNER) + DINNER + dbase + c);
            cpa4(sb + (uint32_t)(B_STG_B   + i) * 4, xdbl  + (size_t)row * XPROJ_N + DTRANK + c);
            cpa4(sb + (uint32_t)(B_STG_C   + i) * 4, xdbl  + (size_t)row * XPROJ_N + DTRANK + DSTATE + c);
        }
        asm volatile("cp.async.commit_group;");
    };

    stage(0, tstart);
    __syncthreads();

    const int NCH = SEG / SCT;             // 8

    for (int c = 0; c < NCH; c++) {
        if (c + 1 < NCH) {
            stage((c + 1) & 1, tstart + (c + 1) * SCT);
            asm volatile("cp.async.wait_group 1;");
        } else {
            asm volatile("cp.async.wait_group 0;");
        }
        __syncthreads();

        float* sDel = sm + B_OFF_STG + (c & 1) * B_STG_SIZE + B_STG_DEL;
        float* sU   = sm + B_OFF_STG + (c & 1) * B_STG_SIZE + B_STG_U;
        float* sZ   = sm + B_OFF_STG + (c & 1) * B_STG_SIZE + B_STG_Z;
        float* sB   = sm + B_OFF_STG + (c & 1) * B_STG_SIZE + B_STG_B;
        float* sC   = sm + B_OFF_STG + (c & 1) * B_STG_SIZE + B_STG_C;
        const int t0 = tstart + c * SCT;

        // serial recurrence
#pragma unroll 8
        for (int tt = 0; tt < SCT; tt++) {
            float dlt = sDel[tt * 16 + td];
            float uu  = sU[tt * 16 + td];
            float bb  = sB[tt * 16 + tn];
            float cc2 = sC[tt * 16 + tn];
            float dA  = __expf(dlt * Aq);
            h = dA * h + (dlt * uu) * bb;
            sP[(tt * 16 + td) * 17 + tn] = h * cc2;
        }
        __syncthreads();

        // parallel reduce over n + gate + fp16 output
#pragma unroll
        for (int v = 0; v < 2; v++) {
            int o = tid + v * 256;
            int tt = o >> 4, cc = o & 15;
            const float* p = sP + (tt * 16 + cc) * 17;
            float s = 0.f;
#pragma unroll
            for (int n = 0; n < 16; n++) s += p[n];
            float uu = sU[tt * 16 + cc];
            float zz = sZ[tt * 16 + cc];
            float yv = s + sdsk[cc] * uu;
            yv *= zz / (1.f + expf(-zz));
            int row = b * LL + t0 + tt;
            yh[(size_t)row * DINNER + dbase + cc] = __float2half(yv);
        }
        __syncthreads();
    }
}

// ---------------------------------------------------------------------------
extern "C" void kernel_launch(void* const* d_in, const int* in_sizes, int n_in,
                              void* d_out, int out_size)
{
    const float* x       = (const float*)d_in[0];
    const float* W_in    = (const float*)d_in[1];
    const float* conv_w  = (const float*)d_in[2];
    const float* conv_b  = (const float*)d_in[3];
    const float* W_xproj = (const float*)d_in[4];
    const float* W_dt    = (const float*)d_in[5];
    const float* b_dt    = (const float*)d_in[6];
    const float* A_log   = (const float*)d_in[7];
    const float* D_skip  = (const float*)d_in[8];
    const float* W_out   = (const float*)d_in[9];
    float* out = (float*)d_out;

    float* xz;    cudaGetSymbolAddress((void**)&xz,    g_xz);
    float* u;     cudaGetSymbolAddress((void**)&u,     g_u);
    float* xdbl;  cudaGetSymbolAddress((void**)&xdbl,  g_xdbl);
    float* xpart; cudaGetSymbolAddress((void**)&xpart, g_xpart);
    float* part;  cudaGetSymbolAddress((void**)&part,  g_part);
    float* delta; cudaGetSymbolAddress((void**)&delta, g_delta);
    float* hend;  cudaGetSymbolAddress((void**)&hend,  g_hend);
    float* acum;  cudaGetSymbolAddress((void**)&acum,  g_acum);
    float* h0;    cudaGetSymbolAddress((void**)&h0,    g_h0);

    __half *xh, *winTh, *winTl, *yh, *woutTh, *woutTl;
    cudaGetSymbolAddress((void**)&xh,     g_xh);
    cudaGetSymbolAddress((void**)&winTh,  g_winT_h);
    cudaGetSymbolAddress((void**)&winTl,  g_winT_l);
    cudaGetSymbolAddress((void**)&yh,     g_yh);
    cudaGetSymbolAddress((void**)&woutTh, g_woutT_h);
    cudaGetSymbolAddress((void**)&woutTl, g_woutT_l);

    cudaFuncSetAttribute(gemm_mma, cudaFuncAttributeMaxDynamicSharedMemorySize, GM_SMEM);
    cudaFuncSetAttribute(scanA, cudaFuncAttributeMaxDynamicSharedMemorySize, SCANA_SMEM);
    cudaFuncSetAttribute(scanB, cudaFuncAttributeMaxDynamicSharedMemorySize, SCANB_SMEM);

    // operand conversions
    conv_fp16<<<(MROWS * DMODEL / 4) / 256, 256>>>(x, xh, MROWS * DMODEL / 4);
    tsplit_fp16<<<dim3(4096 / 32, DMODEL / 32), 256>>>(W_in, winTh, winTl, DMODEL, 4096);
    tsplit_fp16<<<dim3(DMODEL / 32, DINNER / 32), 256>>>(W_out, woutTh, woutTl, DINNER, DMODEL);

    // 1) xz = x @ W_in
    gemm_mma<<<dim3(4096 / 128, MROWS / 128, 1), 256, GM_SMEM>>>(
        xh, winTh, winTl, xz, DMODEL, 4096, DMODEL, 0);

    // 2) u = silu(conv(xz[:, :2048]) + conv_b)
    conv_silu_kernel<<<(MROWS * DINNER / 4 + 255) / 256, 256>>>(xz, conv_w, conv_b, u);

    // 3) xdbl = u @ W_xproj
    xprojA<<<dim3(KSPLITS, MROWS / 64), 256>>>(u, W_xproj, xpart);
    xprojB<<<(MROWS * XPROJ_N + 255) / 256, 256>>>(xpart, xdbl);

    // 4+5) segmented selective scan
    scanA<<<dim3(DINNER / 16, BB, NSEG), 256, SCANA_SMEM>>>(
        u, xdbl, W_dt, b_dt, A_log, delta, hend, acum);
    scan_combine<<<(BB * DINNER * DSTATE + 255) / 256, 256>>>(hend, acum, h0);
    scanB<<<dim3(DINNER / 16, BB, NSEG), 256, SCANB_SMEM>>>(
        u, xz, xdbl, delta, A_log, D_skip, h0, yh);

    // 6) out = y @ W_out  (2-way split-K + reduce)
    gemm_mma<<<dim3(1024 / 128, MROWS / 128, 2), 256, GM_SMEM>>>(
        yh, woutTh, woutTl, part, DINNER, 1024, 1024,
        (size_t)MROWS * DMODEL);
    reduce2<<<(MROWS * DMODEL / 4 + 255) / 256, 256>>>(part, out, MROWS * DMODEL);
}